// round 2
// baseline (speedup 1.0000x reference)
#include <cuda_runtime.h>
#include <math.h>

#define T_   4
#define B_   32
#define C_   384
#define N_   196
#define H_   12
#define D_   32
#define CN_  (C_*N_)            // 75264
#define BCN  (B_*C_*N_)         // 2408448
#define TBCN (T_*B_*C_*N_)      // 9633792
#define JTOT (B_*N_)            // 6272 columns per timestep

// ---------------- scratch (device globals; no allocation allowed) ------------
__device__ float g_qkv[3u * TBCN];     // q,k,v spikes
__device__ float g_att[TBCN];          // attention output -> spikes (in place)
__device__ float g_bnscale[3 * C_];
__device__ float g_bnbias[3 * C_];
__device__ float g_pscale[C_];
__device__ float g_pbias[C_];

// ---------------- f32x2 packed-math helpers ----------------------------------
__device__ __forceinline__ unsigned long long pack2(float lo, float hi) {
    unsigned long long d;
    asm("mov.b64 %0, {%1, %2};" : "=l"(d) : "f"(lo), "f"(hi));
    return d;
}
__device__ __forceinline__ void fma2(unsigned long long& d,
                                     unsigned long long a, unsigned long long b) {
    asm("fma.rn.f32x2 %0, %1, %2, %3;" : "=l"(d) : "l"(a), "l"(b), "l"(d));
}
__device__ __forceinline__ void unpack2(unsigned long long v, float& lo, float& hi) {
    asm("mov.b64 {%0, %1}, %2;" : "=f"(lo), "=f"(hi) : "l"(v));
}

// ---------------- BN coefficient setup ---------------------------------------
__global__ void setup_bn(
    const float* __restrict__ qg, const float* __restrict__ qb, const float* __restrict__ qm, const float* __restrict__ qv,
    const float* __restrict__ kg, const float* __restrict__ kb, const float* __restrict__ km, const float* __restrict__ kv,
    const float* __restrict__ vg, const float* __restrict__ vb, const float* __restrict__ vm, const float* __restrict__ vv,
    const float* __restrict__ pg, const float* __restrict__ pb, const float* __restrict__ pm, const float* __restrict__ pv,
    const float* __restrict__ pbias)
{
    int i = blockIdx.x * blockDim.x + threadIdx.x;
    if (i < 3 * C_) {
        int p = i / C_, c = i - p * C_;
        const float *g, *be, *mu, *va;
        if (p == 0)      { g = qg; be = qb; mu = qm; va = qv; }
        else if (p == 1) { g = kg; be = kb; mu = km; va = kv; }
        else             { g = vg; be = vb; mu = vm; va = vv; }
        float inv = g[c] / sqrtf(va[c] + 1e-5f);
        g_bnscale[i] = inv;
        g_bnbias[i]  = be[c] - mu[c] * inv;
    } else if (i < 4 * C_) {
        int c = i - 3 * C_;
        float inv = pg[c] / sqrtf(pv[c] + 1e-5f);
        g_pscale[c] = inv;
        g_pbias[c]  = pb[c] - pm[c] * inv + pbias[c] * inv;
    }
}

// ---------------- GEMM + BN + fused LIF ---------------------------------------
// Block covers 128 output rows x 64 (b,n) columns; loops t=0..3 internally,
// carrying LIF membrane state in registers; writes spikes.
// f32x2 packed FFMA2 inner loop, BK=16.
__global__ __launch_bounds__(256, 2) void gemm_bn_lif(
    const float* __restrict__ X, const float* __restrict__ w0,
    const float* __restrict__ w1, const float* __restrict__ w2,
    const float* __restrict__ scale, const float* __restrict__ bias,
    float* __restrict__ Y, float thr)
{
    __shared__ __align__(16) float Ws[16 * 132];
    __shared__ __align__(16) float Xs[16 * 64];
    __shared__ int sbase[64];

    int tid = threadIdx.x;
    int j0  = blockIdx.x * 64;
    int o0  = blockIdx.y * 128;
    int p   = o0 / C_;
    const float* w = (p == 0) ? w0 : ((p == 1) ? w1 : w2);
    int om0 = o0 - p * C_;

    if (tid < 64) {
        int j = j0 + tid;
        int b = j / N_;
        int n = j - b * N_;
        sbase[tid] = b * CN_ + n;
    }
    __syncthreads();

    int tx = tid & 15, ty = tid >> 4;
    const float* wrow = &w[(om0 + (tid >> 1)) * C_ + (tid & 1) * 8];
    int wr = tid >> 1, wq = (tid & 1) * 8;

    // LIF membrane state: rows pairs (2ip, 2ip+1), cols j
    float vlo[4][4], vhi[4][4];
#pragma unroll
    for (int i = 0; i < 4; ++i)
#pragma unroll
        for (int j = 0; j < 4; ++j) { vlo[i][j] = 0.f; vhi[i][j] = 0.f; }

    for (int t = 0; t < T_; ++t) {
        unsigned long long acc[4][4];
#pragma unroll
        for (int i = 0; i < 4; ++i)
#pragma unroll
            for (int j = 0; j < 4; ++j) acc[i][j] = 0ull;

        const float* Xt = X + (size_t)t * BCN;

        for (int c0 = 0; c0 < C_; c0 += 16) {
            // W tile: 128 rows x 16 k
            {
                float4 wa = *(const float4*)&wrow[c0];
                float4 wb = *(const float4*)&wrow[c0 + 4];
                Ws[(wq + 0) * 132 + wr] = wa.x;
                Ws[(wq + 1) * 132 + wr] = wa.y;
                Ws[(wq + 2) * 132 + wr] = wa.z;
                Ws[(wq + 3) * 132 + wr] = wa.w;
                Ws[(wq + 4) * 132 + wr] = wb.x;
                Ws[(wq + 5) * 132 + wr] = wb.y;
                Ws[(wq + 6) * 132 + wr] = wb.z;
                Ws[(wq + 7) * 132 + wr] = wb.w;
            }
            // X tile: 16 k x 64 j
#pragma unroll
            for (int u = 0; u < 4; ++u) {
                int idx = tid + u * 256;
                int kk = idx >> 6, jj = idx & 63;
                Xs[kk * 64 + jj] = Xt[sbase[jj] + (c0 + kk) * N_];
            }
            __syncthreads();
#pragma unroll
            for (int kk = 0; kk < 16; ++kk) {
                const longlong2* ap = (const longlong2*)&Ws[kk * 132 + ty * 8];
                longlong2 apq0 = ap[0];   // row pairs (0,1),(2,3)
                longlong2 apq1 = ap[1];   // row pairs (4,5),(6,7)
                float4 bv = *(const float4*)&Xs[kk * 64 + tx * 4];
                unsigned long long b0 = pack2(bv.x, bv.x);
                unsigned long long b1 = pack2(bv.y, bv.y);
                unsigned long long b2 = pack2(bv.z, bv.z);
                unsigned long long b3 = pack2(bv.w, bv.w);
                unsigned long long a0 = (unsigned long long)apq0.x;
                unsigned long long a1 = (unsigned long long)apq0.y;
                unsigned long long a2 = (unsigned long long)apq1.x;
                unsigned long long a3 = (unsigned long long)apq1.y;
                fma2(acc[0][0], a0, b0); fma2(acc[0][1], a0, b1);
                fma2(acc[0][2], a0, b2); fma2(acc[0][3], a0, b3);
                fma2(acc[1][0], a1, b0); fma2(acc[1][1], a1, b1);
                fma2(acc[1][2], a1, b2); fma2(acc[1][3], a1, b3);
                fma2(acc[2][0], a2, b0); fma2(acc[2][1], a2, b1);
                fma2(acc[2][2], a2, b2); fma2(acc[2][3], a2, b3);
                fma2(acc[3][0], a3, b0); fma2(acc[3][1], a3, b1);
                fma2(acc[3][2], a3, b2); fma2(acc[3][3], a3, b3);
            }
            __syncthreads();
        }

        // BN affine + LIF update + spike write for this t
        float* Yt = Y + (size_t)p * TBCN + (size_t)t * BCN;
#pragma unroll
        for (int ip = 0; ip < 4; ++ip) {
            int og = o0 + ty * 8 + 2 * ip;
            float sc0 = scale[og],     bi0 = bias[og];
            float sc1 = scale[og + 1], bi1 = bias[og + 1];
            int om = og - p * C_;
            float* out0 = Yt + om * N_;
            float* out1 = out0 + N_;
#pragma unroll
            for (int j = 0; j < 4; ++j) {
                float y0, y1;
                unpack2(acc[ip][j], y0, y1);
                int sb = sbase[tx * 4 + j];
                float pre0 = y0 * sc0 + bi0;
                float pre1 = y1 * sc1 + bi1;
                float v0 = vlo[ip][j], v1 = vhi[ip][j];
                v0 += (pre0 - v0) * 0.5f;
                v1 += (pre1 - v1) * 0.5f;
                float s0 = (v0 >= thr) ? 1.0f : 0.0f;
                float s1 = (v1 >= thr) ? 1.0f : 0.0f;
                if (s0 != 0.f) v0 = 0.f;
                if (s1 != 0.f) v1 = 0.f;
                vlo[ip][j] = v0; vhi[ip][j] = v1;
                out0[sb] = s0;
                out1[sb] = s1;
            }
        }
        __syncthreads();
    }
}

// ---------------- LIF (elementwise, float4), for attention output -------------
__global__ void lif_kernel(const float* __restrict__ in, float* __restrict__ out,
                           float thr, int total4)
{
    int i = blockIdx.x * blockDim.x + threadIdx.x;
    if (i >= total4) return;
    const int q = BCN / 4;
    const float4* ip = (const float4*)in + i;
    float4*       op = (float4*)out      + i;

    float4 v = make_float4(0.f, 0.f, 0.f, 0.f);
#pragma unroll
    for (int t = 0; t < T_; ++t) {
        float4 x = ip[(size_t)t * q];
        v.x += (x.x - v.x) * 0.5f;  v.y += (x.y - v.y) * 0.5f;
        v.z += (x.z - v.z) * 0.5f;  v.w += (x.w - v.w) * 0.5f;
        float4 s;
        s.x = (v.x >= thr) ? 1.0f : 0.0f;
        s.y = (v.y >= thr) ? 1.0f : 0.0f;
        s.z = (v.z >= thr) ? 1.0f : 0.0f;
        s.w = (v.w >= thr) ? 1.0f : 0.0f;
        op[(size_t)t * q] = s;
        if (s.x != 0.f) v.x = 0.f;
        if (s.y != 0.f) v.y = 0.f;
        if (s.z != 0.f) v.z = 0.f;
        if (s.w != 0.f) v.w = 0.f;
    }
}

// ---------------- Attention (per t,b,h): popcount QK^T, policy, AV ------------
__global__ __launch_bounds__(256) void attn_kernel(
    const float* __restrict__ qkv, const float* __restrict__ policy,
    float* __restrict__ out)
{
    __shared__ __align__(16) float s_v[N_ * 36];
    __shared__ unsigned s_qm[N_], s_km[N_];
    __shared__ float s_pol[N_];

    int tid = threadIdx.x;
    int bz  = blockIdx.x;            // (t*B + b)*H + h
    int h   = bz % H_;
    int tb  = bz / H_;
    int base = tb * CN_ + h * D_ * N_;

    // stage q, build q masks
    for (int idx = tid; idx < D_ * N_; idx += 256) {
        int d = idx / N_, n = idx - d * N_;
        s_v[n * 36 + d] = qkv[base + d * N_ + n];
    }
    __syncthreads();
    int n = tid;
    if (n < N_) {
        unsigned m = 0;
#pragma unroll
        for (int d = 0; d < D_; ++d)
            if (s_v[n * 36 + d] != 0.0f) m |= (1u << d);
        s_qm[n] = m;
    }
    __syncthreads();
    // stage k, build k masks
    for (int idx = tid; idx < D_ * N_; idx += 256) {
        int d = idx / N_, nn = idx - d * N_;
        s_v[nn * 36 + d] = qkv[TBCN + base + d * N_ + nn];
    }
    __syncthreads();
    if (n < N_) {
        unsigned m = 0;
#pragma unroll
        for (int d = 0; d < D_; ++d)
            if (s_v[n * 36 + d] != 0.0f) m |= (1u << d);
        s_km[n] = m;
    }
    __syncthreads();
    // stage v (kept), policy
    for (int idx = tid; idx < D_ * N_; idx += 256) {
        int d = idx / N_, nn = idx - d * N_;
        s_v[nn * 36 + d] = qkv[2 * TBCN + base + d * N_ + nn];
    }
    if (tid < N_) s_pol[tid] = policy[tb * N_ + tid];
    __syncthreads();

    if (n < N_) {
        unsigned long long y2[16];
#pragma unroll
        for (int i = 0; i < 16; ++i) y2[i] = 0ull;
        unsigned qm = s_qm[n];
        for (int m = 0; m < N_; ++m) {
            unsigned kmm = s_km[m];
            if (kmm == 0u) continue;          // warp-uniform skip
            int cnt = __popc(qm & kmm);
            if (cnt == 0) continue;
            float a = (float)cnt * ((m == n) ? 1.0f : s_pol[m]);
            unsigned long long aa = pack2(a, a);
            const longlong2* vp = (const longlong2*)(s_v + m * 36);
#pragma unroll
            for (int q4 = 0; q4 < 8; ++q4) {
                longlong2 vv = vp[q4];
                fma2(y2[2 * q4 + 0], aa, (unsigned long long)vv.x);
                fma2(y2[2 * q4 + 1], aa, (unsigned long long)vv.y);
            }
        }
        // direct coalesced writes (threads n consecutive)
        float* op = out + base + n;
#pragma unroll
        for (int q4 = 0; q4 < 16; ++q4) {
            float lo, hi;
            unpack2(y2[q4], lo, hi);
            op[(2 * q4 + 0) * N_] = lo * 0.25f;
            op[(2 * q4 + 1) * N_] = hi * 0.25f;
        }
    }
}

// ---------------- launch ------------------------------------------------------
extern "C" void kernel_launch(void* const* d_in, const int* in_sizes, int n_in,
                              void* d_out, int out_size)
{
    const float* x      = (const float*)d_in[0];
    const float* policy = (const float*)d_in[1];
    const float* qw = (const float*)d_in[2];
    const float* qg = (const float*)d_in[3];
    const float* qb = (const float*)d_in[4];
    const float* qm = (const float*)d_in[5];
    const float* qv = (const float*)d_in[6];
    const float* kw = (const float*)d_in[7];
    const float* kg = (const float*)d_in[8];
    const float* kb = (const float*)d_in[9];
    const float* km = (const float*)d_in[10];
    const float* kv = (const float*)d_in[11];
    const float* vw = (const float*)d_in[12];
    const float* vg = (const float*)d_in[13];
    const float* vb = (const float*)d_in[14];
    const float* vm = (const float*)d_in[15];
    const float* vv = (const float*)d_in[16];
    const float* pw = (const float*)d_in[17];
    const float* pg = (const float*)d_in[18];
    const float* pb = (const float*)d_in[19];
    const float* pm = (const float*)d_in[20];
    const float* pv = (const float*)d_in[21];
    const float* pbias = (const float*)d_in[22];

    float *qkv_p, *att_p, *bns_p, *bnb_p, *ps_p, *pbs_p;
    cudaGetSymbolAddress((void**)&qkv_p, g_qkv);
    cudaGetSymbolAddress((void**)&att_p, g_att);
    cudaGetSymbolAddress((void**)&bns_p, g_bnscale);
    cudaGetSymbolAddress((void**)&bnb_p, g_bnbias);
    cudaGetSymbolAddress((void**)&ps_p,  g_pscale);
    cudaGetSymbolAddress((void**)&pbs_p, g_pbias);

    setup_bn<<<6, 256>>>(qg, qb, qm, qv, kg, kb, km, kv, vg, vb, vm, vv,
                         pg, pb, pm, pv, pbias);

    // q,k,v conv+bn+LIF fused: spikes out
    gemm_bn_lif<<<dim3(JTOT / 64, 9), 256>>>(x, qw, kw, vw, bns_p, bnb_p,
                                             qkv_p, 1.0f);

    // attention per (t,b,h)
    attn_kernel<<<T_ * B_ * H_, 256>>>(qkv_p, policy, att_p);

    // LIF(theta=0.5) on attention output, in place
    lif_kernel<<<(BCN / 4 + 255) / 256, 256>>>(att_p, att_p, 0.5f, BCN / 4);

    // proj conv+bias+bn+LIF fused -> d_out
    gemm_bn_lif<<<dim3(JTOT / 64, 3), 256>>>(att_p, pw, pw, pw, ps_p, pbs_p,
                                             (float*)d_out, 1.0f);
}

// round 4
// speedup vs baseline: 2.1671x; 2.1671x over previous
#include <cuda_runtime.h>
#include <cuda_bf16.h>
#include <math.h>

#define T_   4
#define B_   32
#define C_   384
#define N_   196
#define H_   12
#define D_   32
#define CN_  (C_*N_)            // 75264
#define BCN  (B_*C_*N_)         // 2408448
#define TBCN (T_*B_*C_*N_)      // 9633792
#define JTOT (B_*N_*T_)         // 25088 tokens
#define WQKV (1152*384)         // 442368
#define WPRJ (384*384)          // 147456

// ---------------- scratch (device globals; no allocation allowed) ------------
__device__ float g_qkv[3u * TBCN];          // q,k,v preact -> spikes (in place)
__device__ float g_att[TBCN];               // attention out -> spikes -> proj preact
__device__ __nv_bfloat16 g_xs[3u * TBCN];   // split X, [part][j][c] K-major
__device__ __nv_bfloat16 g_ss[TBCN];        // spike input of proj, [j][c] K-major
__device__ __nv_bfloat16 g_ws[3u * WQKV];   // split qkv weights [part][o_glob][c]
__device__ __nv_bfloat16 g_ps[3u * WPRJ];   // split proj weights
__device__ float g_bnscale[3 * C_];
__device__ float g_bnbias[3 * C_];
__device__ float g_pscale[C_];
__device__ float g_pbias[C_];

// ---------------- helpers ------------------------------------------------------
__device__ __forceinline__ unsigned smem_to_u32(const void* p) {
    unsigned a;
    asm("{ .reg .u64 t; cvta.to.shared.u64 t, %1; cvt.u32.u64 %0, t; }"
        : "=r"(a) : "l"(p));
    return a;
}
__device__ __forceinline__ void ldsm4(unsigned& r0, unsigned& r1,
                                      unsigned& r2, unsigned& r3, unsigned addr) {
    asm volatile("ldmatrix.sync.aligned.m8n8.x4.shared.b16 {%0,%1,%2,%3}, [%4];"
        : "=r"(r0), "=r"(r1), "=r"(r2), "=r"(r3) : "r"(addr));
}
__device__ __forceinline__ void mma16816(float* c, const unsigned* a, const unsigned* b) {
    asm volatile(
        "mma.sync.aligned.m16n8k16.row.col.f32.bf16.bf16.f32 "
        "{%0,%1,%2,%3}, {%4,%5,%6,%7}, {%8,%9}, {%0,%1,%2,%3};"
        : "+f"(c[0]), "+f"(c[1]), "+f"(c[2]), "+f"(c[3])
        : "r"(a[0]), "r"(a[1]), "r"(a[2]), "r"(a[3]), "r"(b[0]), "r"(b[1]));
}
__device__ __forceinline__ void split3(float x, __nv_bfloat16& h,
                                       __nv_bfloat16& m, __nv_bfloat16& l) {
    h = __float2bfloat16(x);
    float r = x - __bfloat162float(h);
    m = __float2bfloat16(r);
    float r2 = r - __bfloat162float(m);
    l = __float2bfloat16(r2);
}

// ---------------- BN coefficient setup ---------------------------------------
__global__ void setup_bn(
    const float* __restrict__ qg, const float* __restrict__ qb, const float* __restrict__ qm, const float* __restrict__ qv,
    const float* __restrict__ kg, const float* __restrict__ kb, const float* __restrict__ km, const float* __restrict__ kv,
    const float* __restrict__ vg, const float* __restrict__ vb, const float* __restrict__ vm, const float* __restrict__ vv,
    const float* __restrict__ pg, const float* __restrict__ pb, const float* __restrict__ pm, const float* __restrict__ pv,
    const float* __restrict__ pbias)
{
    int i = blockIdx.x * blockDim.x + threadIdx.x;
    if (i < 3 * C_) {
        int p = i / C_, c = i - p * C_;
        const float *g, *be, *mu, *va;
        if (p == 0)      { g = qg; be = qb; mu = qm; va = qv; }
        else if (p == 1) { g = kg; be = kb; mu = km; va = kv; }
        else             { g = vg; be = vb; mu = vm; va = vv; }
        float inv = g[c] / sqrtf(va[c] + 1e-5f);
        g_bnscale[i] = inv;
        g_bnbias[i]  = be[c] - mu[c] * inv;
    } else if (i < 4 * C_) {
        int c = i - 3 * C_;
        float inv = pg[c] / sqrtf(pv[c] + 1e-5f);
        g_pscale[c] = inv;
        g_pbias[c]  = pb[c] - pm[c] * inv + pbias[c] * inv;
    }
}

// ---------------- weight split (qkv stacked 1152 rows + proj 384) -------------
__global__ void wsplit(const float* __restrict__ qw, const float* __restrict__ kw,
                       const float* __restrict__ vw, const float* __restrict__ pw)
{
    int i = blockIdx.x * blockDim.x + threadIdx.x;
    if (i < WQKV) {
        int o = i / 384, c = i - o * 384;
        const float* w = (o < 384) ? qw : ((o < 768) ? kw : vw);
        float x = w[(o % 384) * 384 + c];
        __nv_bfloat16 h, m, l;
        split3(x, h, m, l);
        g_ws[i] = h; g_ws[WQKV + i] = m; g_ws[2 * WQKV + i] = l;
    } else if (i < WQKV + WPRJ) {
        int k = i - WQKV;
        float x = pw[k];
        __nv_bfloat16 h, m, l;
        split3(x, h, m, l);
        g_ps[k] = h; g_ps[WPRJ + k] = m; g_ps[2 * WPRJ + k] = l;
    }
}

// ---------------- X split + transpose to [j][c] K-major -----------------------
__global__ __launch_bounds__(256) void xsplit(const float* __restrict__ X)
{
    __shared__ float tile[64 * 65];
    __shared__ int cb[64];
    int tid = threadIdx.x;
    int j0 = blockIdx.x * 64, c0 = blockIdx.y * 64;
    if (tid < 64) {
        int j = j0 + tid;
        int t = j / (B_ * N_);
        int r = j - t * (B_ * N_);
        int b = r / N_;
        int n = r - b * N_;
        cb[tid] = (t * B_ + b) * CN_ + n;
    }
    __syncthreads();
#pragma unroll
    for (int u = 0; u < 16; ++u) {
        int idx = u * 256 + tid;
        int cc = idx >> 6, jj = idx & 63;
        tile[cc * 65 + jj] = X[(size_t)cb[jj] + (size_t)(c0 + cc) * N_];
    }
    __syncthreads();
#pragma unroll
    for (int u = 0; u < 16; ++u) {
        int idx = u * 256 + tid;
        int jj = idx >> 6, cc = idx & 63;
        float x = tile[cc * 65 + jj];
        __nv_bfloat16 h, m, l;
        split3(x, h, m, l);
        size_t o = (size_t)(j0 + jj) * 384 + c0 + cc;
        g_xs[o] = h; g_xs[TBCN + o] = m; g_xs[2u * TBCN + o] = l;
    }
}

// ---------------- spike transpose to [j][c] bf16 (exact) ----------------------
__global__ __launch_bounds__(256) void strans(const float* __restrict__ S)
{
    __shared__ float tile[64 * 65];
    __shared__ int cb[64];
    int tid = threadIdx.x;
    int j0 = blockIdx.x * 64, c0 = blockIdx.y * 64;
    if (tid < 64) {
        int j = j0 + tid;
        int t = j / (B_ * N_);
        int r = j - t * (B_ * N_);
        int b = r / N_;
        int n = r - b * N_;
        cb[tid] = (t * B_ + b) * CN_ + n;
    }
    __syncthreads();
#pragma unroll
    for (int u = 0; u < 16; ++u) {
        int idx = u * 256 + tid;
        int cc = idx >> 6, jj = idx & 63;
        tile[cc * 65 + jj] = S[(size_t)cb[jj] + (size_t)(c0 + cc) * N_];
    }
    __syncthreads();
#pragma unroll
    for (int u = 0; u < 16; ++u) {
        int idx = u * 256 + tid;
        int jj = idx >> 6, cc = idx & 63;
        g_ss[(size_t)(j0 + jj) * 384 + c0 + cc] = __float2bfloat16(tile[cc * 65 + jj]);
    }
}

// ---------------- tensor-core GEMM (mma.sync bf16) + BN ------------------------
// D[o,j] = sum_c W[o,c]*X[j,c]; exact via bf16 3-term splitting.
// Tile 128(o) x 128(j), BK=32. 8 warps in 2(m) x 4(n); warp tile 64x32.
// Smem tiles: rows padded to 80B (40 bf16) -> conflict-free ldmatrix.
#define TPAD   80
#define TILEB  (128 * TPAD)          // 10240
#define GSMEM  (6 * TILEB + 512)     // + sbase

template <int NB6>
__global__ __launch_bounds__(256) void gemm_mma(
    const __nv_bfloat16* __restrict__ A, size_t APS,
    const __nv_bfloat16* __restrict__ Bm, size_t BPS,
    const float* __restrict__ scale, const float* __restrict__ bias,
    float* __restrict__ Y)
{
    extern __shared__ __align__(16) char dsm[];
    unsigned smt = smem_to_u32(dsm);
    int* sbase = (int*)(dsm + 6 * TILEB);

    int tid = threadIdx.x;
    int wid = tid >> 5, lane = tid & 31;
    int wm = wid & 1, wn = wid >> 1;
    int j0 = blockIdx.x * 128;
    int o0 = blockIdx.y * 128;

    if (tid < 128) {
        int j = j0 + tid;
        int t = j / (B_ * N_);
        int r = j - t * (B_ * N_);
        int b = r / N_;
        int n = r - b * N_;
        sbase[tid] = (t * B_ + b) * CN_ + n;
    }

    // ldmatrix lane address components
    int a_row = (lane & 7) + ((lane >> 3) & 1) * 8;
    int a_k   = (lane >> 4) * 8;
    int b_n   = (lane & 7) + (lane >> 4) * 8;
    int b_k   = ((lane >> 3) & 1) * 8;

    float acc[4][4][4];
#pragma unroll
    for (int i = 0; i < 4; ++i)
#pragma unroll
        for (int j = 0; j < 4; ++j)
#pragma unroll
            for (int r = 0; r < 4; ++r) acc[i][j][r] = 0.0f;

    const int NBT = NB6 ? 3 : 1;   // number of B tiles to load

    int ldrow = tid >> 2, ldg = tid & 3;

    for (int ch = 0; ch < 12; ++ch) {
        int c0 = ch * 32;
        // load 3 A-part tiles + NBT B-part tiles
#pragma unroll
        for (int p = 0; p < 3; ++p) {
            const __nv_bfloat16* src = A + (size_t)p * APS + (size_t)(o0 + ldrow) * 384 + c0 + ldg * 8;
            char* dst = dsm + p * TILEB + ldrow * TPAD + ldg * 16;
            *(uint4*)dst = *(const uint4*)src;
            *(uint4*)(dst + 64 * TPAD) = *(const uint4*)(src + (size_t)64 * 384);
        }
#pragma unroll
        for (int p = 0; p < NBT; ++p) {
            const __nv_bfloat16* src = Bm + (size_t)p * BPS + (size_t)(j0 + ldrow) * 384 + c0 + ldg * 8;
            char* dst = dsm + (3 + p) * TILEB + ldrow * TPAD + ldg * 16;
            *(uint4*)dst = *(const uint4*)src;
            *(uint4*)(dst + 64 * TPAD) = *(const uint4*)(src + (size_t)64 * 384);
        }
        __syncthreads();

#pragma unroll
        for (int ks = 0; ks < 2; ++ks) {
            int k0 = ks * 16;
#pragma unroll
            for (int pa = 0; pa < 3; ++pa) {
                unsigned afr[4][4];
#pragma unroll
                for (int mt = 0; mt < 4; ++mt) {
                    unsigned ad = smt + pa * TILEB
                                + (wm * 64 + mt * 16 + a_row) * TPAD
                                + (k0 + a_k) * 2;
                    ldsm4(afr[mt][0], afr[mt][1], afr[mt][2], afr[mt][3], ad);
                }
                const int npb = NB6 ? (3 - pa) : 1;   // (0,0)(0,1)(0,2)(1,0)(1,1)(2,0)
#pragma unroll
                for (int pb = 0; pb < npb; ++pb) {
                    unsigned bfr[2][4];
#pragma unroll
                    for (int half = 0; half < 2; ++half) {
                        unsigned bd = smt + (3 + pb) * TILEB
                                    + (wn * 32 + half * 16 + b_n) * TPAD
                                    + (k0 + b_k) * 2;
                        ldsm4(bfr[half][0], bfr[half][1], bfr[half][2], bfr[half][3], bd);
                    }
#pragma unroll
                    for (int mt = 0; mt < 4; ++mt)
#pragma unroll
                        for (int nt = 0; nt < 4; ++nt)
                            mma16816(acc[mt][nt], afr[mt], &bfr[nt >> 1][(nt & 1) * 2]);
                }
            }
        }
        __syncthreads();
    }

    // epilogue: BN affine + store
    int p   = o0 / C_;
    int om0 = o0 - p * C_;
    float* Yp = Y + (size_t)p * TBCN;
#pragma unroll
    for (int mt = 0; mt < 4; ++mt) {
        int mbase = wm * 64 + mt * 16 + (lane >> 2);
#pragma unroll
        for (int rh = 0; rh < 2; ++rh) {
            int orow = o0 + mbase + rh * 8;
            float sc = scale[orow], bi = bias[orow];
            float* rp = Yp + (size_t)(om0 + mbase + rh * 8) * N_;
#pragma unroll
            for (int nt = 0; nt < 4; ++nt) {
                int jl = wn * 32 + nt * 8 + (lane & 3) * 2;
                rp[sbase[jl]]     = acc[mt][nt][rh * 2 + 0] * sc + bi;
                rp[sbase[jl + 1]] = acc[mt][nt][rh * 2 + 1] * sc + bi;
            }
        }
    }
}

// ---------------- LIF (sequential over T, elementwise, float4) ----------------
__global__ void lif_kernel(const float* __restrict__ in, float* __restrict__ out,
                           float thr, int total4)
{
    int i = blockIdx.x * blockDim.x + threadIdx.x;
    if (i >= total4) return;
    const int q = BCN / 4;
    int p = i / q;
    int r = i - p * q;
    const float4* ip = (const float4*)in + (size_t)p * (TBCN / 4) + r;
    float4*       op = (float4*)out      + (size_t)p * (TBCN / 4) + r;

    float4 v = make_float4(0.f, 0.f, 0.f, 0.f);
#pragma unroll
    for (int t = 0; t < T_; ++t) {
        float4 x = ip[(size_t)t * q];
        v.x += (x.x - v.x) * 0.5f;  v.y += (x.y - v.y) * 0.5f;
        v.z += (x.z - v.z) * 0.5f;  v.w += (x.w - v.w) * 0.5f;
        float4 s;
        s.x = (v.x >= thr) ? 1.0f : 0.0f;
        s.y = (v.y >= thr) ? 1.0f : 0.0f;
        s.z = (v.z >= thr) ? 1.0f : 0.0f;
        s.w = (v.w >= thr) ? 1.0f : 0.0f;
        op[(size_t)t * q] = s;
        if (s.x != 0.f) v.x = 0.f;
        if (s.y != 0.f) v.y = 0.f;
        if (s.z != 0.f) v.z = 0.f;
        if (s.w != 0.f) v.w = 0.f;
    }
}

// ---------------- Attention (per t,b,h): popcount QK^T, policy, AV ------------
__global__ __launch_bounds__(256) void attn_kernel(
    const float* __restrict__ qkv, const float* __restrict__ policy,
    float* __restrict__ out)
{
    __shared__ __align__(16) float s_v[N_ * 36];
    __shared__ unsigned s_qm[N_], s_km[N_];
    __shared__ float s_pol[N_];

    int tid = threadIdx.x;
    int bz  = blockIdx.x;            // (t*B + b)*H + h
    int h   = bz % H_;
    int tb  = bz / H_;
    int base = tb * CN_ + h * D_ * N_;

    for (int idx = tid; idx < D_ * N_; idx += 256) {
        int d = idx / N_, n = idx - d * N_;
        s_v[n * 36 + d] = qkv[base + d * N_ + n];
    }
    __syncthreads();
    int n = tid;
    if (n < N_) {
        unsigned m = 0;
#pragma unroll
        for (int d = 0; d < D_; ++d)
            if (s_v[n * 36 + d] != 0.0f) m |= (1u << d);
        s_qm[n] = m;
    }
    __syncthreads();
    for (int idx = tid; idx < D_ * N_; idx += 256) {
        int d = idx / N_, nn = idx - d * N_;
        s_v[nn * 36 + d] = qkv[TBCN + base + d * N_ + nn];
    }
    __syncthreads();
    if (n < N_) {
        unsigned m = 0;
#pragma unroll
        for (int d = 0; d < D_; ++d)
            if (s_v[n * 36 + d] != 0.0f) m |= (1u << d);
        s_km[n] = m;
    }
    __syncthreads();
    for (int idx = tid; idx < D_ * N_; idx += 256) {
        int d = idx / N_, nn = idx - d * N_;
        s_v[nn * 36 + d] = qkv[2u * TBCN + base + d * N_ + nn];
    }
    if (tid < N_) s_pol[tid] = policy[tb * N_ + tid];
    __syncthreads();

    if (n < N_) {
        float y[D_];
#pragma unroll
        for (int d = 0; d < D_; ++d) y[d] = 0.0f;
        unsigned qm = s_qm[n];
        for (int m = 0; m < N_; ++m) {
            unsigned kmm = s_km[m];
            if (kmm == 0u) continue;
            int cnt = __popc(qm & kmm);
            if (cnt == 0) continue;
            float a = (float)cnt * ((m == n) ? 1.0f : s_pol[m]);
            const float4* vp = (const float4*)(s_v + m * 36);
#pragma unroll
            for (int q4 = 0; q4 < 8; ++q4) {
                float4 vv = vp[q4];
                y[4 * q4 + 0] += a * vv.x;
                y[4 * q4 + 1] += a * vv.y;
                y[4 * q4 + 2] += a * vv.z;
                y[4 * q4 + 3] += a * vv.w;
            }
        }
        float* op = out + base + n;
#pragma unroll
        for (int d = 0; d < D_; ++d)
            op[d * N_] = y[d] * 0.25f;
    }
}

// ---------------- launch ------------------------------------------------------
extern "C" void kernel_launch(void* const* d_in, const int* in_sizes, int n_in,
                              void* d_out, int out_size)
{
    const float* x      = (const float*)d_in[0];
    const float* policy = (const float*)d_in[1];
    const float* qw = (const float*)d_in[2];
    const float* qg = (const float*)d_in[3];
    const float* qb = (const float*)d_in[4];
    const float* qm = (const float*)d_in[5];
    const float* qv = (const float*)d_in[6];
    const float* kw = (const float*)d_in[7];
    const float* kg = (const float*)d_in[8];
    const float* kb = (const float*)d_in[9];
    const float* km = (const float*)d_in[10];
    const float* kv = (const float*)d_in[11];
    const float* vw = (const float*)d_in[12];
    const float* vg = (const float*)d_in[13];
    const float* vb = (const float*)d_in[14];
    const float* vm = (const float*)d_in[15];
    const float* vv = (const float*)d_in[16];
    const float* pw = (const float*)d_in[17];
    const float* pg = (const float*)d_in[18];
    const float* pb = (const float*)d_in[19];
    const float* pm = (const float*)d_in[20];
    const float* pv = (const float*)d_in[21];
    const float* pbias = (const float*)d_in[22];

    float *qkv_p, *att_p, *bns_p, *bnb_p, *ps_p, *pbs_p;
    __nv_bfloat16 *xs_p, *ss_p, *ws_p, *pws_p;
    cudaGetSymbolAddress((void**)&qkv_p, g_qkv);
    cudaGetSymbolAddress((void**)&att_p, g_att);
    cudaGetSymbolAddress((void**)&bns_p, g_bnscale);
    cudaGetSymbolAddress((void**)&bnb_p, g_bnbias);
    cudaGetSymbolAddress((void**)&ps_p,  g_pscale);
    cudaGetSymbolAddress((void**)&pbs_p, g_pbias);
    cudaGetSymbolAddress((void**)&xs_p,  g_xs);
    cudaGetSymbolAddress((void**)&ss_p,  g_ss);
    cudaGetSymbolAddress((void**)&ws_p,  g_ws);
    cudaGetSymbolAddress((void**)&pws_p, g_ps);

    cudaFuncSetAttribute(gemm_mma<1>, cudaFuncAttributeMaxDynamicSharedMemorySize, GSMEM);
    cudaFuncSetAttribute(gemm_mma<0>, cudaFuncAttributeMaxDynamicSharedMemorySize, GSMEM);

    setup_bn<<<6, 256>>>(qg, qb, qm, qv, kg, kb, km, kv, vg, vb, vm, vv,
                         pg, pb, pm, pv, pbias);
    wsplit<<<(WQKV + WPRJ + 255) / 256, 256>>>(qw, kw, vw, pw);
    xsplit<<<dim3(JTOT / 64, C_ / 64), 256>>>(x);

    // qkv GEMM: [1152x384] @ [384x25088], 6-term split
    gemm_mma<1><<<dim3(JTOT / 128, 9), 256, GSMEM>>>(
        ws_p, (size_t)WQKV, xs_p, (size_t)TBCN, bns_p, bnb_p, qkv_p);

    // LIF(theta=1) over q,k,v in place
    lif_kernel<<<(3 * BCN / 4 + 255) / 256, 256>>>(qkv_p, qkv_p, 1.0f, 3 * BCN / 4);

    // attention per (t,b,h)
    attn_kernel<<<T_ * B_ * H_, 256>>>(qkv_p, policy, att_p);

    // LIF(theta=0.5) in place
    lif_kernel<<<(BCN / 4 + 255) / 256, 256>>>(att_p, att_p, 0.5f, BCN / 4);

    // spikes -> K-major bf16 (exact)
    strans<<<dim3(JTOT / 64, C_ / 64), 256>>>(att_p);

    // proj GEMM: [384x384] @ [384x25088], 3-term (B exact) -> g_att preact... write to qkv scratch
    gemm_mma<0><<<dim3(JTOT / 128, 3), 256, GSMEM>>>(
        pws_p, (size_t)WPRJ, ss_p, (size_t)0, ps_p, pbs_p, qkv_p);

    // final LIF(theta=1) -> d_out
    lif_kernel<<<(BCN / 4 + 255) / 256, 256>>>(qkv_p, (float*)d_out, 1.0f, BCN / 4);
}

// round 7
// speedup vs baseline: 2.6422x; 1.2192x over previous
#include <cuda_runtime.h>
#include <cuda_fp16.h>
#include <math.h>

#define T_   4
#define B_   32
#define C_   384
#define N_   196
#define H_   12
#define D_   32
#define CN_  (C_*N_)            // 75264
#define BCN  (B_*C_*N_)         // 2408448
#define TBCN (T_*B_*C_*N_)      // 9633792
#define JTOT (B_*N_*T_)         // 25088 tokens
#define WQKV (1152*384)         // 442368
#define WPRJ (384*384)          // 147456
#define INV2048 4.8828125e-4f

// ---------------- scratch (device globals; no allocation allowed) ------------
__device__ float g_qkv[3u * TBCN];        // q,k,v preact -> spikes (in place); proj scratch
__device__ float g_att[TBCN];             // attention out -> spikes
__device__ __half g_xs[2u * TBCN];        // split X: [part][j][c] K-major
__device__ __half g_ss[TBCN];             // proj spike input, [j][c] K-major (exact)
__device__ __half g_ws[2u * WQKV];        // split qkv weights [part][o][c]
__device__ __half g_ps[2u * WPRJ];        // split proj weights
__device__ float g_bnscale[3 * C_];
__device__ float g_bnbias[3 * C_];
__device__ float g_pscale[C_];
__device__ float g_pbias[C_];

// ---------------- helpers ------------------------------------------------------
__device__ __forceinline__ unsigned smem_to_u32(const void* p) {
    unsigned a;
    asm("{ .reg .u64 t; cvta.to.shared.u64 t, %1; cvt.u32.u64 %0, t; }"
        : "=r"(a) : "l"(p));
    return a;
}
__device__ __forceinline__ void ldsm4(unsigned& r0, unsigned& r1,
                                      unsigned& r2, unsigned& r3, unsigned addr) {
    asm volatile("ldmatrix.sync.aligned.m8n8.x4.shared.b16 {%0,%1,%2,%3}, [%4];"
        : "=r"(r0), "=r"(r1), "=r"(r2), "=r"(r3) : "r"(addr));
}
__device__ __forceinline__ void mma16816h(float* c, const unsigned* a, const unsigned* b) {
    asm volatile(
        "mma.sync.aligned.m16n8k16.row.col.f32.f16.f16.f32 "
        "{%0,%1,%2,%3}, {%4,%5,%6,%7}, {%8,%9}, {%0,%1,%2,%3};"
        : "+f"(c[0]), "+f"(c[1]), "+f"(c[2]), "+f"(c[3])
        : "r"(a[0]), "r"(a[1]), "r"(a[2]), "r"(a[3]), "r"(b[0]), "r"(b[1]));
}
__device__ __forceinline__ void split2h(float x, __half& h, __half& m) {
    h = __float2half_rn(x);
    float r = x - __half2float(h);
    m = __float2half_rn(r * 2048.0f);    // scaled residual: always normal range
}
// f32x2 packed math
__device__ __forceinline__ unsigned long long pack2(float lo, float hi) {
    unsigned long long d;
    asm("mov.b64 %0, {%1, %2};" : "=l"(d) : "f"(lo), "f"(hi));
    return d;
}
__device__ __forceinline__ void fma2(unsigned long long& d,
                                     unsigned long long a, unsigned long long b) {
    asm("fma.rn.f32x2 %0, %1, %2, %3;" : "=l"(d) : "l"(a), "l"(b), "l"(d));
}
__device__ __forceinline__ void unpack2(unsigned long long v, float& lo, float& hi) {
    asm("mov.b64 {%0, %1}, %2;" : "=f"(lo), "=f"(hi) : "l"(v));
}

// ---------------- BN coefficient setup ---------------------------------------
__global__ void setup_bn(
    const float* __restrict__ qg, const float* __restrict__ qb, const float* __restrict__ qm, const float* __restrict__ qv,
    const float* __restrict__ kg, const float* __restrict__ kb, const float* __restrict__ km, const float* __restrict__ kv,
    const float* __restrict__ vg, const float* __restrict__ vb, const float* __restrict__ vm, const float* __restrict__ vv,
    const float* __restrict__ pg, const float* __restrict__ pb, const float* __restrict__ pm, const float* __restrict__ pv,
    const float* __restrict__ pbias)
{
    int i = blockIdx.x * blockDim.x + threadIdx.x;
    if (i < 3 * C_) {
        int p = i / C_, c = i - p * C_;
        const float *g, *be, *mu, *va;
        if (p == 0)      { g = qg; be = qb; mu = qm; va = qv; }
        else if (p == 1) { g = kg; be = kb; mu = km; va = kv; }
        else             { g = vg; be = vb; mu = vm; va = vv; }
        float inv = g[c] / sqrtf(va[c] + 1e-5f);
        g_bnscale[i] = inv;
        g_bnbias[i]  = be[c] - mu[c] * inv;
    } else if (i < 4 * C_) {
        int c = i - 3 * C_;
        float inv = pg[c] / sqrtf(pv[c] + 1e-5f);
        g_pscale[c] = inv;
        g_pbias[c]  = pb[c] - pm[c] * inv + pbias[c] * inv;
    }
}

// ---------------- weight split (qkv stacked 1152 rows + proj 384) -------------
__global__ void wsplit(const float* __restrict__ qw, const float* __restrict__ kw,
                       const float* __restrict__ vw, const float* __restrict__ pw)
{
    int i = blockIdx.x * blockDim.x + threadIdx.x;
    if (i < WQKV) {
        int o = i / 384, c = i - o * 384;
        const float* w = (o < 384) ? qw : ((o < 768) ? kw : vw);
        float x = w[(o % 384) * 384 + c];
        __half h, m;
        split2h(x, h, m);
        g_ws[i] = h; g_ws[WQKV + i] = m;
    } else if (i < WQKV + WPRJ) {
        int k = i - WQKV;
        __half h, m;
        split2h(pw[k], h, m);
        g_ps[k] = h; g_ps[WPRJ + k] = m;
    }
}

// ---------------- X split + transpose to [j][c] K-major -----------------------
__global__ __launch_bounds__(256) void xsplit(const float* __restrict__ X)
{
    __shared__ float tile[64 * 65];
    __shared__ int cb[64];
    int tid = threadIdx.x;
    int j0 = blockIdx.x * 64, c0 = blockIdx.y * 64;
    if (tid < 64) {
        int j = j0 + tid;
        int t = j / (B_ * N_);
        int r = j - t * (B_ * N_);
        int b = r / N_;
        int n = r - b * N_;
        cb[tid] = (t * B_ + b) * CN_ + n;
    }
    __syncthreads();
#pragma unroll
    for (int u = 0; u < 16; ++u) {
        int idx = u * 256 + tid;
        int cc = idx >> 6, jj = idx & 63;
        tile[cc * 65 + jj] = X[(size_t)cb[jj] + (size_t)(c0 + cc) * N_];
    }
    __syncthreads();
#pragma unroll
    for (int u = 0; u < 16; ++u) {
        int idx = u * 256 + tid;
        int jj = idx >> 6, cc = idx & 63;
        __half h, m;
        split2h(tile[cc * 65 + jj], h, m);
        size_t o = (size_t)(j0 + jj) * 384 + c0 + cc;
        g_xs[o] = h; g_xs[TBCN + o] = m;
    }
}

// ---------------- spike transpose to [j][c] fp16 (exact) ----------------------
__global__ __launch_bounds__(256) void strans(const float* __restrict__ S)
{
    __shared__ float tile[64 * 65];
    __shared__ int cb[64];
    int tid = threadIdx.x;
    int j0 = blockIdx.x * 64, c0 = blockIdx.y * 64;
    if (tid < 64) {
        int j = j0 + tid;
        int t = j / (B_ * N_);
        int r = j - t * (B_ * N_);
        int b = r / N_;
        int n = r - b * N_;
        cb[tid] = (t * B_ + b) * CN_ + n;
    }
    __syncthreads();
#pragma unroll
    for (int u = 0; u < 16; ++u) {
        int idx = u * 256 + tid;
        int cc = idx >> 6, jj = idx & 63;
        tile[cc * 65 + jj] = S[(size_t)cb[jj] + (size_t)(c0 + cc) * N_];
    }
    __syncthreads();
#pragma unroll
    for (int u = 0; u < 16; ++u) {
        int idx = u * 256 + tid;
        int jj = idx >> 6, cc = idx & 63;
        g_ss[(size_t)(j0 + jj) * 384 + c0 + cc] = __float2half_rn(tile[cc * 65 + jj]);
    }
}

// ---------------- tensor-core GEMM (mma.sync fp16 2-term split) + BN ----------
// D[o,j] = sum_c W[o,c]*X[j,c]; W = h + m*2^-11 (m stored scaled by 2^11).
// NBP=2: X also split (acc0 += hh; acc1 += hm + mh). NBP=1: X exact fp16
// (acc0 += hX; acc1 += mX). Final: (acc0 + 2^-11*acc1).
// Tile 64(o) x 128(j), BK=32. 8 warps in 2(m) x 4(n); warp tile 32x32.
#define TPAD   80
#define ATB    (64 * TPAD)
#define BTB    (128 * TPAD)

template <int NBP>
__global__ __launch_bounds__(256) void gemm_mma(
    const __half* __restrict__ A, size_t APS,
    const __half* __restrict__ Bm, size_t BPS,
    const float* __restrict__ scale, const float* __restrict__ bias,
    float* __restrict__ Y)
{
    __shared__ __align__(16) char dsm[2 * ATB + 2 * BTB];
    __shared__ int sbase[128];
    unsigned smt = smem_to_u32(dsm);

    int tid = threadIdx.x;
    int wid = tid >> 5, lane = tid & 31;
    int wm = wid & 1, wn = wid >> 1;
    int j0 = blockIdx.x * 128;
    int o0 = blockIdx.y * 64;

    if (tid < 128) {
        int j = j0 + tid;
        int t = j / (B_ * N_);
        int r = j - t * (B_ * N_);
        int b = r / N_;
        int n = r - b * N_;
        sbase[tid] = (t * B_ + b) * CN_ + n;
    }

    int a_row = lane & 15;
    int a_k   = (lane >> 4) * 8;
    int b_n   = (lane & 7) + (lane >> 4) * 8;
    int b_k   = ((lane >> 3) & 1) * 8;

    float acc0[2][4][4], acc1[2][4][4];
#pragma unroll
    for (int i = 0; i < 2; ++i)
#pragma unroll
        for (int j = 0; j < 4; ++j)
#pragma unroll
            for (int r = 0; r < 4; ++r) { acc0[i][j][r] = 0.f; acc1[i][j][r] = 0.f; }

    int ldrow = tid >> 2, ldg = tid & 3;

    for (int ch = 0; ch < 12; ++ch) {
        int c0 = ch * 32;
#pragma unroll
        for (int p = 0; p < 2; ++p) {
            const __half* src = A + (size_t)p * APS + (size_t)(o0 + ldrow) * 384 + c0 + ldg * 8;
            *(uint4*)(dsm + p * ATB + ldrow * TPAD + ldg * 16) = *(const uint4*)src;
        }
#pragma unroll
        for (int p = 0; p < NBP; ++p) {
            const __half* src = Bm + (size_t)p * BPS + (size_t)(j0 + ldrow) * 384 + c0 + ldg * 8;
            char* dst = dsm + 2 * ATB + p * BTB + ldrow * TPAD + ldg * 16;
            *(uint4*)dst = *(const uint4*)src;
            *(uint4*)(dst + 64 * TPAD) = *(const uint4*)(src + (size_t)64 * 384);
        }
        __syncthreads();

#pragma unroll
        for (int ks = 0; ks < 2; ++ks) {
            int k0 = ks * 16;
            unsigned ah[2][4], am[2][4];
#pragma unroll
            for (int mt = 0; mt < 2; ++mt) {
                unsigned ad = smt + (wm * 32 + mt * 16 + a_row) * TPAD + (k0 + a_k) * 2;
                ldsm4(ah[mt][0], ah[mt][1], ah[mt][2], ah[mt][3], ad);
                ldsm4(am[mt][0], am[mt][1], am[mt][2], am[mt][3], ad + ATB);
            }
            unsigned bh[2][4];
#pragma unroll
            for (int half = 0; half < 2; ++half) {
                unsigned bd = smt + 2 * ATB + (wn * 32 + half * 16 + b_n) * TPAD + (k0 + b_k) * 2;
                ldsm4(bh[half][0], bh[half][1], bh[half][2], bh[half][3], bd);
            }
            if (NBP == 2) {
                unsigned bm[2][4];
#pragma unroll
                for (int half = 0; half < 2; ++half) {
                    unsigned bd = smt + 2 * ATB + BTB + (wn * 32 + half * 16 + b_n) * TPAD + (k0 + b_k) * 2;
                    ldsm4(bm[half][0], bm[half][1], bm[half][2], bm[half][3], bd);
                }
#pragma unroll
                for (int mt = 0; mt < 2; ++mt)
#pragma unroll
                    for (int nt = 0; nt < 4; ++nt) {
                        mma16816h(acc0[mt][nt], ah[mt], &bh[nt >> 1][(nt & 1) * 2]);
                        mma16816h(acc1[mt][nt], ah[mt], &bm[nt >> 1][(nt & 1) * 2]);
                        mma16816h(acc1[mt][nt], am[mt], &bh[nt >> 1][(nt & 1) * 2]);
                    }
            } else {
#pragma unroll
                for (int mt = 0; mt < 2; ++mt)
#pragma unroll
                    for (int nt = 0; nt < 4; ++nt) {
                        mma16816h(acc0[mt][nt], ah[mt], &bh[nt >> 1][(nt & 1) * 2]);
                        mma16816h(acc1[mt][nt], am[mt], &bh[nt >> 1][(nt & 1) * 2]);
                    }
            }
        }
        __syncthreads();
    }

    // epilogue: combine scales, BN affine, store
    int p   = o0 / C_;
    int om0 = o0 - p * C_;
    float* Yp = Y + (size_t)p * TBCN;
#pragma unroll
    for (int mt = 0; mt < 2; ++mt) {
        int mbase = wm * 32 + mt * 16 + (lane >> 2);
#pragma unroll
        for (int rh = 0; rh < 2; ++rh) {
            int orow = o0 + mbase + rh * 8;
            float sc = scale[orow], bi = bias[orow];
            float* rp = Yp + (size_t)(om0 + mbase + rh * 8) * N_;
#pragma unroll
            for (int nt = 0; nt < 4; ++nt) {
                int jl = wn * 32 + nt * 8 + (lane & 3) * 2;
                float v0 = acc0[mt][nt][rh * 2 + 0] + INV2048 * acc1[mt][nt][rh * 2 + 0];
                float v1 = acc0[mt][nt][rh * 2 + 1] + INV2048 * acc1[mt][nt][rh * 2 + 1];
                rp[sbase[jl]]     = v0 * sc + bi;
                rp[sbase[jl + 1]] = v1 * sc + bi;
            }
        }
    }
}

// ---------------- LIF (sequential over T, elementwise, float4) ----------------
__global__ void lif_kernel(const float* __restrict__ in, float* __restrict__ out,
                           float thr, int total4)
{
    int i = blockIdx.x * blockDim.x + threadIdx.x;
    if (i >= total4) return;
    const int q = BCN / 4;
    int p = i / q;
    int r = i - p * q;
    const float4* ip = (const float4*)in + (size_t)p * (TBCN / 4) + r;
    float4*       op = (float4*)out      + (size_t)p * (TBCN / 4) + r;

    float4 v = make_float4(0.f, 0.f, 0.f, 0.f);
#pragma unroll
    for (int t = 0; t < T_; ++t) {
        float4 x = ip[(size_t)t * q];
        v.x += (x.x - v.x) * 0.5f;  v.y += (x.y - v.y) * 0.5f;
        v.z += (x.z - v.z) * 0.5f;  v.w += (x.w - v.w) * 0.5f;
        float4 s;
        s.x = (v.x >= thr) ? 1.0f : 0.0f;
        s.y = (v.y >= thr) ? 1.0f : 0.0f;
        s.z = (v.z >= thr) ? 1.0f : 0.0f;
        s.w = (v.w >= thr) ? 1.0f : 0.0f;
        op[(size_t)t * q] = s;
        if (s.x != 0.f) v.x = 0.f;
        if (s.y != 0.f) v.y = 0.f;
        if (s.z != 0.f) v.z = 0.f;
        if (s.w != 0.f) v.w = 0.f;
    }
}

// ---------------- Attention (per t,b,h): popcount QK^T, policy, AV ------------
__global__ __launch_bounds__(256) void attn_kernel(
    const float* __restrict__ qkv, const float* __restrict__ policy,
    float* __restrict__ out)
{
    __shared__ __align__(16) float s_v[N_ * 36];
    __shared__ unsigned s_qm[N_], s_km[N_];
    __shared__ float s_pol[N_];

    int tid = threadIdx.x;
    int bz  = blockIdx.x;            // (t*B + b)*H + h
    int h   = bz % H_;
    int tb  = bz / H_;
    int base = tb * CN_ + h * D_ * N_;

    for (int idx = tid; idx < D_ * N_; idx += 256) {
        int d = idx / N_, n = idx - d * N_;
        s_v[n * 36 + d] = qkv[base + d * N_ + n];
    }
    __syncthreads();
    int n = tid;
    if (n < N_) {
        unsigned m = 0;
#pragma unroll
        for (int d = 0; d < D_; ++d)
            if (s_v[n * 36 + d] != 0.0f) m |= (1u << d);
        s_qm[n] = m;
    }
    __syncthreads();
    for (int idx = tid; idx < D_ * N_; idx += 256) {
        int d = idx / N_, nn = idx - d * N_;
        s_v[nn * 36 + d] = qkv[TBCN + base + d * N_ + nn];
    }
    __syncthreads();
    if (n < N_) {
        unsigned m = 0;
#pragma unroll
        for (int d = 0; d < D_; ++d)
            if (s_v[n * 36 + d] != 0.0f) m |= (1u << d);
        s_km[n] = m;
    }
    __syncthreads();
    for (int idx = tid; idx < D_ * N_; idx += 256) {
        int d = idx / N_, nn = idx - d * N_;
        s_v[nn * 36 + d] = qkv[2u * TBCN + base + d * N_ + nn];
    }
    if (tid < N_) s_pol[tid] = policy[tb * N_ + tid];
    __syncthreads();

    if (n < N_) {
        unsigned long long y2[16];
#pragma unroll
        for (int i = 0; i < 16; ++i) y2[i] = 0ull;
        unsigned qm = s_qm[n];
        for (int m = 0; m < N_; ++m) {
            unsigned kmm = s_km[m];
            if (kmm == 0u) continue;          // warp-uniform skip
            int cnt = __popc(qm & kmm);
            if (cnt == 0) continue;
            float a = (float)cnt * ((m == n) ? 1.0f : s_pol[m]);
            unsigned long long aa = pack2(a, a);
            const longlong2* vp = (const longlong2*)(s_v + m * 36);
#pragma unroll
            for (int q4 = 0; q4 < 8; ++q4) {
                longlong2 vv = vp[q4];
                fma2(y2[2 * q4 + 0], aa, (unsigned long long)vv.x);
                fma2(y2[2 * q4 + 1], aa, (unsigned long long)vv.y);
            }
        }
        float* op = out + base + n;
#pragma unroll
        for (int q4 = 0; q4 < 16; ++q4) {
            float lo, hi;
            unpack2(y2[q4], lo, hi);
            op[(2 * q4 + 0) * N_] = lo * 0.25f;
            op[(2 * q4 + 1) * N_] = hi * 0.25f;
        }
    }
}

// ---------------- launch ------------------------------------------------------
extern "C" void kernel_launch(void* const* d_in, const int* in_sizes, int n_in,
                              void* d_out, int out_size)
{
    const float* x      = (const float*)d_in[0];
    const float* policy = (const float*)d_in[1];
    const float* qw = (const float*)d_in[2];
    const float* qg = (const float*)d_in[3];
    const float* qb = (const float*)d_in[4];
    const float* qm = (const float*)d_in[5];
    const float* qv = (const float*)d_in[6];
    const float* kw = (const float*)d_in[7];
    const float* kg = (const float*)d_in[8];
    const float* kb = (const float*)d_in[9];
    const float* km = (const float*)d_in[10];
    const float* kv = (const float*)d_in[11];
    const float* vw = (const float*)d_in[12];
    const float* vg = (const float*)d_in[13];
    const float* vb = (const float*)d_in[14];
    const float* vm = (const float*)d_in[15];
    const float* vv = (const float*)d_in[16];
    const float* pw = (const float*)d_in[17];
    const float* pg = (const float*)d_in[18];
    const float* pb = (const float*)d_in[19];
    const float* pm = (const float*)d_in[20];
    const float* pv = (const float*)d_in[21];
    const float* pbias = (const float*)d_in[22];

    float *qkv_p, *att_p, *bns_p, *bnb_p, *ps_p, *pbs_p;
    __half *xs_p, *ss_p, *ws_p, *pws_p;
    cudaGetSymbolAddress((void**)&qkv_p, g_qkv);
    cudaGetSymbolAddress((void**)&att_p, g_att);
    cudaGetSymbolAddress((void**)&bns_p, g_bnscale);
    cudaGetSymbolAddress((void**)&bnb_p, g_bnbias);
    cudaGetSymbolAddress((void**)&ps_p,  g_pscale);
    cudaGetSymbolAddress((void**)&pbs_p, g_pbias);
    cudaGetSymbolAddress((void**)&xs_p,  g_xs);
    cudaGetSymbolAddress((void**)&ss_p,  g_ss);
    cudaGetSymbolAddress((void**)&ws_p,  g_ws);
    cudaGetSymbolAddress((void**)&pws_p, g_ps);

    setup_bn<<<6, 256>>>(qg, qb, qm, qv, kg, kb, km, kv, vg, vb, vm, vv,
                         pg, pb, pm, pv, pbias);
    wsplit<<<(WQKV + WPRJ + 255) / 256, 256>>>(qw, kw, vw, pw);
    xsplit<<<dim3(JTOT / 64, C_ / 64), 256>>>(x);

    // qkv GEMM: [1152x384] @ [384x25088], fp16 2-term split (3 products)
    gemm_mma<2><<<dim3(JTOT / 128, 1152 / 64), 256>>>(
        ws_p, (size_t)WQKV, xs_p, (size_t)TBCN, bns_p, bnb_p, qkv_p);

    // LIF(theta=1) over q,k,v in place
    lif_kernel<<<(3 * BCN / 4 + 255) / 256, 256>>>(qkv_p, qkv_p, 1.0f, 3 * BCN / 4);

    // attention per (t,b,h)
    attn_kernel<<<T_ * B_ * H_, 256>>>(qkv_p, policy, att_p);

    // LIF(theta=0.5) in place
    lif_kernel<<<(BCN / 4 + 255) / 256, 256>>>(att_p, att_p, 0.5f, BCN / 4);

    // spikes -> K-major fp16 (exact)
    strans<<<dim3(JTOT / 64, C_ / 64), 256>>>(att_p);

    // proj GEMM: [384x384] @ [384x25088], A split, B exact (2 products) -> qkv scratch
    gemm_mma<1><<<dim3(JTOT / 128, 384 / 64), 256>>>(
        pws_p, (size_t)WPRJ, ss_p, (size_t)0, ps_p, pbs_p, qkv_p);

    // final LIF(theta=1) -> d_out
    lif_kernel<<<(BCN / 4 + 255) / 256, 256>>>(qkv_p, (float*)d_out, 1.0f, BCN / 4);
}

// round 8
// speedup vs baseline: 2.8696x; 1.0861x over previous
#include <cuda_runtime.h>
#include <cuda_fp16.h>
#include <math.h>

#define T_   4
#define B_   32
#define C_   384
#define N_   196
#define H_   12
#define D_   32
#define CN_  (C_*N_)            // 75264
#define BCN  (B_*C_*N_)         // 2408448
#define TBCN (T_*B_*C_*N_)      // 9633792
#define JTOT (B_*N_*T_)         // 25088 tokens
#define WQKV (1152*384)         // 442368
#define WPRJ (384*384)          // 147456
#define INV2048 4.8828125e-4f

// ---------------- scratch (device globals; no allocation allowed) ------------
__device__ float g_qkv[3u * TBCN];        // q,k,v preact -> spikes (in place); proj scratch
__device__ float g_att[TBCN];             // attention out -> spikes
__device__ __half g_xs[2u * TBCN];        // split X: [part][j][c] K-major
__device__ __half g_ss[TBCN];             // proj spike input, [j][c] K-major (exact)
__device__ __half g_ws[2u * WQKV];        // split qkv weights [part][o][c]
__device__ __half g_ps[2u * WPRJ];        // split proj weights
__device__ float g_bnscale[3 * C_];
__device__ float g_bnbias[3 * C_];
__device__ float g_pscale[C_];
__device__ float g_pbias[C_];

// ---------------- helpers ------------------------------------------------------
__device__ __forceinline__ unsigned smem_to_u32(const void* p) {
    unsigned a;
    asm("{ .reg .u64 t; cvta.to.shared.u64 t, %1; cvt.u32.u64 %0, t; }"
        : "=r"(a) : "l"(p));
    return a;
}
__device__ __forceinline__ void ldsm4(unsigned& r0, unsigned& r1,
                                      unsigned& r2, unsigned& r3, unsigned addr) {
    asm volatile("ldmatrix.sync.aligned.m8n8.x4.shared.b16 {%0,%1,%2,%3}, [%4];"
        : "=r"(r0), "=r"(r1), "=r"(r2), "=r"(r3) : "r"(addr));
}
__device__ __forceinline__ void mma16816h(float* c, const unsigned* a, const unsigned* b) {
    asm volatile(
        "mma.sync.aligned.m16n8k16.row.col.f32.f16.f16.f32 "
        "{%0,%1,%2,%3}, {%4,%5,%6,%7}, {%8,%9}, {%0,%1,%2,%3};"
        : "+f"(c[0]), "+f"(c[1]), "+f"(c[2]), "+f"(c[3])
        : "r"(a[0]), "r"(a[1]), "r"(a[2]), "r"(a[3]), "r"(b[0]), "r"(b[1]));
}
__device__ __forceinline__ void cpasync16(unsigned dst, const void* src) {
    asm volatile("cp.async.cg.shared.global [%0], [%1], 16;"
        :: "r"(dst), "l"(src) : "memory");
}
#define CP_COMMIT() asm volatile("cp.async.commit_group;" ::: "memory")
#define CP_WAIT1()  asm volatile("cp.async.wait_group 1;" ::: "memory")
__device__ __forceinline__ void split2h(float x, __half& h, __half& m) {
    h = __float2half_rn(x);
    float r = x - __half2float(h);
    m = __float2half_rn(r * 2048.0f);    // scaled residual: always normal range
}
// f32x2 packed math
__device__ __forceinline__ unsigned long long pack2(float lo, float hi) {
    unsigned long long d;
    asm("mov.b64 %0, {%1, %2};" : "=l"(d) : "f"(lo), "f"(hi));
    return d;
}
__device__ __forceinline__ void fma2(unsigned long long& d,
                                     unsigned long long a, unsigned long long b) {
    asm("fma.rn.f32x2 %0, %1, %2, %3;" : "=l"(d) : "l"(a), "l"(b), "l"(d));
}
__device__ __forceinline__ void unpack2(unsigned long long v, float& lo, float& hi) {
    asm("mov.b64 {%0, %1}, %2;" : "=f"(lo), "=f"(hi) : "l"(v));
}

// ---------------- BN coefficient setup ---------------------------------------
__global__ void setup_bn(
    const float* __restrict__ qg, const float* __restrict__ qb, const float* __restrict__ qm, const float* __restrict__ qv,
    const float* __restrict__ kg, const float* __restrict__ kb, const float* __restrict__ km, const float* __restrict__ kv,
    const float* __restrict__ vg, const float* __restrict__ vb, const float* __restrict__ vm, const float* __restrict__ vv,
    const float* __restrict__ pg, const float* __restrict__ pb, const float* __restrict__ pm, const float* __restrict__ pv,
    const float* __restrict__ pbias)
{
    int i = blockIdx.x * blockDim.x + threadIdx.x;
    if (i < 3 * C_) {
        int p = i / C_, c = i - p * C_;
        const float *g, *be, *mu, *va;
        if (p == 0)      { g = qg; be = qb; mu = qm; va = qv; }
        else if (p == 1) { g = kg; be = kb; mu = km; va = kv; }
        else             { g = vg; be = vb; mu = vm; va = vv; }
        float inv = g[c] / sqrtf(va[c] + 1e-5f);
        g_bnscale[i] = inv;
        g_bnbias[i]  = be[c] - mu[c] * inv;
    } else if (i < 4 * C_) {
        int c = i - 3 * C_;
        float inv = pg[c] / sqrtf(pv[c] + 1e-5f);
        g_pscale[c] = inv;
        g_pbias[c]  = pb[c] - pm[c] * inv + pbias[c] * inv;
    }
}

// ---------------- weight split (qkv stacked 1152 rows + proj 384) -------------
__global__ void wsplit(const float* __restrict__ qw, const float* __restrict__ kw,
                       const float* __restrict__ vw, const float* __restrict__ pw)
{
    int i = blockIdx.x * blockDim.x + threadIdx.x;
    if (i < WQKV) {
        int o = i / 384, c = i - o * 384;
        const float* w = (o < 384) ? qw : ((o < 768) ? kw : vw);
        float x = w[(o % 384) * 384 + c];
        __half h, m;
        split2h(x, h, m);
        g_ws[i] = h; g_ws[WQKV + i] = m;
    } else if (i < WQKV + WPRJ) {
        int k = i - WQKV;
        __half h, m;
        split2h(pw[k], h, m);
        g_ps[k] = h; g_ps[WPRJ + k] = m;
    }
}

// ---------------- X split + transpose to [j][c] K-major -----------------------
__global__ __launch_bounds__(256) void xsplit(const float* __restrict__ X)
{
    __shared__ float tile[64 * 65];
    __shared__ int cb[64];
    int tid = threadIdx.x;
    int j0 = blockIdx.x * 64, c0 = blockIdx.y * 64;
    if (tid < 64) {
        int j = j0 + tid;
        int t = j / (B_ * N_);
        int r = j - t * (B_ * N_);
        int b = r / N_;
        int n = r - b * N_;
        cb[tid] = (t * B_ + b) * CN_ + n;
    }
    __syncthreads();
#pragma unroll
    for (int u = 0; u < 16; ++u) {
        int idx = u * 256 + tid;
        int cc = idx >> 6, jj = idx & 63;
        tile[cc * 65 + jj] = X[(size_t)cb[jj] + (size_t)(c0 + cc) * N_];
    }
    __syncthreads();
#pragma unroll
    for (int u = 0; u < 16; ++u) {
        int idx = u * 256 + tid;
        int jj = idx >> 6, cc = idx & 63;
        __half h, m;
        split2h(tile[cc * 65 + jj], h, m);
        size_t o = (size_t)(j0 + jj) * 384 + c0 + cc;
        g_xs[o] = h; g_xs[TBCN + o] = m;
    }
}

// ---------------- spike transpose to [j][c] fp16 (exact) ----------------------
__global__ __launch_bounds__(256) void strans(const float* __restrict__ S)
{
    __shared__ float tile[64 * 65];
    __shared__ int cb[64];
    int tid = threadIdx.x;
    int j0 = blockIdx.x * 64, c0 = blockIdx.y * 64;
    if (tid < 64) {
        int j = j0 + tid;
        int t = j / (B_ * N_);
        int r = j - t * (B_ * N_);
        int b = r / N_;
        int n = r - b * N_;
        cb[tid] = (t * B_ + b) * CN_ + n;
    }
    __syncthreads();
#pragma unroll
    for (int u = 0; u < 16; ++u) {
        int idx = u * 256 + tid;
        int cc = idx >> 6, jj = idx & 63;
        tile[cc * 65 + jj] = S[(size_t)cb[jj] + (size_t)(c0 + cc) * N_];
    }
    __syncthreads();
#pragma unroll
    for (int u = 0; u < 16; ++u) {
        int idx = u * 256 + tid;
        int jj = idx >> 6, cc = idx & 63;
        g_ss[(size_t)(j0 + jj) * 384 + c0 + cc] = __float2half_rn(tile[cc * 65 + jj]);
    }
}

// ---------------- tensor-core GEMM (fp16 2-term split, cp.async 2-stage) ------
// D[o,j] = sum_c W[o,c]*X[j,c]; W = h + m*2^-11 (m stored scaled by 2^11).
// NBP=2: X split too (acc0 += hh; acc1 += hm + mh). NBP=1: X exact
// (acc0 += hX; acc1 += mX). Final: acc0 + 2^-11*acc1.
// Tile 64(o) x 128(j), BK=32, 2-stage cp.async double buffer.
#define TPAD   80
#define ATB    (64 * TPAD)     // 5120
#define BTB    (128 * TPAD)    // 10240

template <int NBP>
__device__ __forceinline__ void stage_load(
    unsigned sb, const __half* __restrict__ A, size_t APS,
    const __half* __restrict__ Bm, size_t BPS,
    int o0, int j0, int c0, int ldrow, int ldg)
{
#pragma unroll
    for (int p = 0; p < 2; ++p) {
        const __half* src = A + (size_t)p * APS + (size_t)(o0 + ldrow) * 384 + c0 + ldg * 8;
        cpasync16(sb + p * ATB + ldrow * TPAD + ldg * 16, src);
    }
#pragma unroll
    for (int p = 0; p < NBP; ++p) {
        const __half* src = Bm + (size_t)p * BPS + (size_t)(j0 + ldrow) * 384 + c0 + ldg * 8;
        unsigned dst = sb + 2 * ATB + p * BTB + ldrow * TPAD + ldg * 16;
        cpasync16(dst, src);
        cpasync16(dst + 64 * TPAD, src + (size_t)64 * 384);
    }
}

template <int NBP>
__global__ __launch_bounds__(256) void gemm_mma(
    const __half* __restrict__ A, size_t APS,
    const __half* __restrict__ Bm, size_t BPS,
    const float* __restrict__ scale, const float* __restrict__ bias,
    float* __restrict__ Y)
{
    constexpr int STGB = 2 * ATB + NBP * BTB;
    extern __shared__ __align__(16) char dsm[];
    __shared__ int sbase[128];
    unsigned smt = smem_to_u32(dsm);

    int tid = threadIdx.x;
    int wid = tid >> 5, lane = tid & 31;
    int wm = wid & 1, wn = wid >> 1;
    int j0 = blockIdx.x * 128;
    int o0 = blockIdx.y * 64;

    if (tid < 128) {
        int j = j0 + tid;
        int t = j / (B_ * N_);
        int r = j - t * (B_ * N_);
        int b = r / N_;
        int n = r - b * N_;
        sbase[tid] = (t * B_ + b) * CN_ + n;
    }

    int a_row = lane & 15;
    int a_k   = (lane >> 4) * 8;
    int b_n   = (lane & 7) + (lane >> 4) * 8;
    int b_k   = ((lane >> 3) & 1) * 8;

    float acc0[2][4][4], acc1[2][4][4];
#pragma unroll
    for (int i = 0; i < 2; ++i)
#pragma unroll
        for (int j = 0; j < 4; ++j)
#pragma unroll
            for (int r = 0; r < 4; ++r) { acc0[i][j][r] = 0.f; acc1[i][j][r] = 0.f; }

    int ldrow = tid >> 2, ldg = tid & 3;

    // prologue: stage 0
    stage_load<NBP>(smt, A, APS, Bm, BPS, o0, j0, 0, ldrow, ldg);
    CP_COMMIT();

    for (int ch = 0; ch < 12; ++ch) {
        if (ch + 1 < 12)
            stage_load<NBP>(smt + ((ch + 1) & 1) * STGB, A, APS, Bm, BPS,
                            o0, j0, (ch + 1) * 32, ldrow, ldg);
        CP_COMMIT();
        CP_WAIT1();
        __syncthreads();

        unsigned sb = smt + (ch & 1) * STGB;
#pragma unroll
        for (int ks = 0; ks < 2; ++ks) {
            int k0 = ks * 16;
            unsigned ah[2][4], am[2][4];
#pragma unroll
            for (int mt = 0; mt < 2; ++mt) {
                unsigned ad = sb + (wm * 32 + mt * 16 + a_row) * TPAD + (k0 + a_k) * 2;
                ldsm4(ah[mt][0], ah[mt][1], ah[mt][2], ah[mt][3], ad);
                ldsm4(am[mt][0], am[mt][1], am[mt][2], am[mt][3], ad + ATB);
            }
            unsigned bh[2][4];
#pragma unroll
            for (int half = 0; half < 2; ++half) {
                unsigned bd = sb + 2 * ATB + (wn * 32 + half * 16 + b_n) * TPAD + (k0 + b_k) * 2;
                ldsm4(bh[half][0], bh[half][1], bh[half][2], bh[half][3], bd);
            }
            if (NBP == 2) {
                unsigned bm[2][4];
#pragma unroll
                for (int half = 0; half < 2; ++half) {
                    unsigned bd = sb + 2 * ATB + BTB + (wn * 32 + half * 16 + b_n) * TPAD + (k0 + b_k) * 2;
                    ldsm4(bm[half][0], bm[half][1], bm[half][2], bm[half][3], bd);
                }
#pragma unroll
                for (int mt = 0; mt < 2; ++mt)
#pragma unroll
                    for (int nt = 0; nt < 4; ++nt) {
                        mma16816h(acc0[mt][nt], ah[mt], &bh[nt >> 1][(nt & 1) * 2]);
                        mma16816h(acc1[mt][nt], ah[mt], &bm[nt >> 1][(nt & 1) * 2]);
                        mma16816h(acc1[mt][nt], am[mt], &bh[nt >> 1][(nt & 1) * 2]);
                    }
            } else {
#pragma unroll
                for (int mt = 0; mt < 2; ++mt)
#pragma unroll
                    for (int nt = 0; nt < 4; ++nt) {
                        mma16816h(acc0[mt][nt], ah[mt], &bh[nt >> 1][(nt & 1) * 2]);
                        mma16816h(acc1[mt][nt], am[mt], &bh[nt >> 1][(nt & 1) * 2]);
                    }
            }
        }
        __syncthreads();
    }

    // epilogue: combine scales, BN affine, store
    int p   = o0 / C_;
    int om0 = o0 - p * C_;
    float* Yp = Y + (size_t)p * TBCN;
#pragma unroll
    for (int mt = 0; mt < 2; ++mt) {
        int mbase = wm * 32 + mt * 16 + (lane >> 2);
#pragma unroll
        for (int rh = 0; rh < 2; ++rh) {
            int orow = o0 + mbase + rh * 8;
            float sc = scale[orow], bi = bias[orow];
            float* rp = Yp + (size_t)(om0 + mbase + rh * 8) * N_;
#pragma unroll
            for (int nt = 0; nt < 4; ++nt) {
                int jl = wn * 32 + nt * 8 + (lane & 3) * 2;
                float v0 = acc0[mt][nt][rh * 2 + 0] + INV2048 * acc1[mt][nt][rh * 2 + 0];
                float v1 = acc0[mt][nt][rh * 2 + 1] + INV2048 * acc1[mt][nt][rh * 2 + 1];
                rp[sbase[jl]]     = v0 * sc + bi;
                rp[sbase[jl + 1]] = v1 * sc + bi;
            }
        }
    }
}

// ---------------- LIF (sequential over T, elementwise, float4) ----------------
__global__ void lif_kernel(const float* __restrict__ in, float* __restrict__ out,
                           float thr, int total4)
{
    int i = blockIdx.x * blockDim.x + threadIdx.x;
    if (i >= total4) return;
    const int q = BCN / 4;
    int p = i / q;
    int r = i - p * q;
    const float4* ip = (const float4*)in + (size_t)p * (TBCN / 4) + r;
    float4*       op = (float4*)out      + (size_t)p * (TBCN / 4) + r;

    float4 v = make_float4(0.f, 0.f, 0.f, 0.f);
#pragma unroll
    for (int t = 0; t < T_; ++t) {
        float4 x = ip[(size_t)t * q];
        v.x += (x.x - v.x) * 0.5f;  v.y += (x.y - v.y) * 0.5f;
        v.z += (x.z - v.z) * 0.5f;  v.w += (x.w - v.w) * 0.5f;
        float4 s;
        s.x = (v.x >= thr) ? 1.0f : 0.0f;
        s.y = (v.y >= thr) ? 1.0f : 0.0f;
        s.z = (v.z >= thr) ? 1.0f : 0.0f;
        s.w = (v.w >= thr) ? 1.0f : 0.0f;
        op[(size_t)t * q] = s;
        if (s.x != 0.f) v.x = 0.f;
        if (s.y != 0.f) v.y = 0.f;
        if (s.z != 0.f) v.z = 0.f;
        if (s.w != 0.f) v.w = 0.f;
    }
}

// ---------------- Attention (per t,b,h): popcount QK^T, policy, AV ------------
__global__ __launch_bounds__(256) void attn_kernel(
    const float* __restrict__ qkv, const float* __restrict__ policy,
    float* __restrict__ out)
{
    __shared__ __align__(16) float s_v[N_ * 36];
    __shared__ unsigned s_qm[N_], s_km[N_];
    __shared__ float s_pol[N_];

    int tid = threadIdx.x;
    int bz  = blockIdx.x;            // (t*B + b)*H + h
    int h   = bz % H_;
    int tb  = bz / H_;
    int base = tb * CN_ + h * D_ * N_;

    for (int idx = tid; idx < D_ * N_; idx += 256) {
        int d = idx / N_, n = idx - d * N_;
        s_v[n * 36 + d] = qkv[base + d * N_ + n];
    }
    __syncthreads();
    int n = tid;
    if (n < N_) {
        unsigned m = 0;
#pragma unroll
        for (int d = 0; d < D_; ++d)
            if (s_v[n * 36 + d] != 0.0f) m |= (1u << d);
        s_qm[n] = m;
    }
    __syncthreads();
    for (int idx = tid; idx < D_ * N_; idx += 256) {
        int d = idx / N_, nn = idx - d * N_;
        s_v[nn * 36 + d] = qkv[TBCN + base + d * N_ + nn];
    }
    __syncthreads();
    if (n < N_) {
        unsigned m = 0;
#pragma unroll
        for (int d = 0; d < D_; ++d)
            if (s_v[n * 36 + d] != 0.0f) m |= (1u << d);
        s_km[n] = m;
    }
    __syncthreads();
    for (int idx = tid; idx < D_ * N_; idx += 256) {
        int d = idx / N_, nn = idx - d * N_;
        s_v[nn * 36 + d] = qkv[2u * TBCN + base + d * N_ + nn];
    }
    if (tid < N_) s_pol[tid] = policy[tb * N_ + tid];
    __syncthreads();

    if (n < N_) {
        unsigned long long y2[16];
#pragma unroll
        for (int i = 0; i < 16; ++i) y2[i] = 0ull;
        unsigned qm = s_qm[n];
        for (int m = 0; m < N_; ++m) {
            unsigned kmm = s_km[m];
            if (kmm == 0u) continue;          // warp-uniform skip
            int cnt = __popc(qm & kmm);
            if (cnt == 0) continue;
            float a = (float)cnt * ((m == n) ? 1.0f : s_pol[m]);
            unsigned long long aa = pack2(a, a);
            const longlong2* vp = (const longlong2*)(s_v + m * 36);
#pragma unroll
            for (int q4 = 0; q4 < 8; ++q4) {
                longlong2 vv = vp[q4];
                fma2(y2[2 * q4 + 0], aa, (unsigned long long)vv.x);
                fma2(y2[2 * q4 + 1], aa, (unsigned long long)vv.y);
            }
        }
        float* op = out + base + n;
#pragma unroll
        for (int q4 = 0; q4 < 16; ++q4) {
            float lo, hi;
            unpack2(y2[q4], lo, hi);
            op[(2 * q4 + 0) * N_] = lo * 0.25f;
            op[(2 * q4 + 1) * N_] = hi * 0.25f;
        }
    }
}

// ---------------- launch ------------------------------------------------------
extern "C" void kernel_launch(void* const* d_in, const int* in_sizes, int n_in,
                              void* d_out, int out_size)
{
    const float* x      = (const float*)d_in[0];
    const float* policy = (const float*)d_in[1];
    const float* qw = (const float*)d_in[2];
    const float* qg = (const float*)d_in[3];
    const float* qb = (const float*)d_in[4];
    const float* qm = (const float*)d_in[5];
    const float* qv = (const float*)d_in[6];
    const float* kw = (const float*)d_in[7];
    const float* kg = (const float*)d_in[8];
    const float* kb = (const float*)d_in[9];
    const float* km = (const float*)d_in[10];
    const float* kv = (const float*)d_in[11];
    const float* vw = (const float*)d_in[12];
    const float* vg = (const float*)d_in[13];
    const float* vb = (const float*)d_in[14];
    const float* vm = (const float*)d_in[15];
    const float* vv = (const float*)d_in[16];
    const float* pw = (const float*)d_in[17];
    const float* pg = (const float*)d_in[18];
    const float* pb = (const float*)d_in[19];
    const float* pm = (const float*)d_in[20];
    const float* pv = (const float*)d_in[21];
    const float* pbias = (const float*)d_in[22];

    float *qkv_p, *att_p, *bns_p, *bnb_p, *ps_p, *pbs_p;
    __half *xs_p, *ss_p, *ws_p, *pws_p;
    cudaGetSymbolAddress((void**)&qkv_p, g_qkv);
    cudaGetSymbolAddress((void**)&att_p, g_att);
    cudaGetSymbolAddress((void**)&bns_p, g_bnscale);
    cudaGetSymbolAddress((void**)&bnb_p, g_bnbias);
    cudaGetSymbolAddress((void**)&ps_p,  g_pscale);
    cudaGetSymbolAddress((void**)&pbs_p, g_pbias);
    cudaGetSymbolAddress((void**)&xs_p,  g_xs);
    cudaGetSymbolAddress((void**)&ss_p,  g_ss);
    cudaGetSymbolAddress((void**)&ws_p,  g_ws);
    cudaGetSymbolAddress((void**)&pws_p, g_ps);

    const int SM2 = 2 * (2 * ATB + 2 * BTB);   // 61440
    const int SM1 = 2 * (2 * ATB + 1 * BTB);   // 40960
    cudaFuncSetAttribute(gemm_mma<2>, cudaFuncAttributeMaxDynamicSharedMemorySize, SM2);
    cudaFuncSetAttribute(gemm_mma<1>, cudaFuncAttributeMaxDynamicSharedMemorySize, SM1);

    setup_bn<<<6, 256>>>(qg, qb, qm, qv, kg, kb, km, kv, vg, vb, vm, vv,
                         pg, pb, pm, pv, pbias);
    wsplit<<<(WQKV + WPRJ + 255) / 256, 256>>>(qw, kw, vw, pw);
    xsplit<<<dim3(JTOT / 64, C_ / 64), 256>>>(x);

    // qkv GEMM: [1152x384] @ [384x25088], fp16 2-term split (3 products)
    gemm_mma<2><<<dim3(JTOT / 128, 1152 / 64), 256, SM2>>>(
        ws_p, (size_t)WQKV, xs_p, (size_t)TBCN, bns_p, bnb_p, qkv_p);

    // LIF(theta=1) over q,k,v in place
    lif_kernel<<<(3 * BCN / 4 + 255) / 256, 256>>>(qkv_p, qkv_p, 1.0f, 3 * BCN / 4);

    // attention per (t,b,h)
    attn_kernel<<<T_ * B_ * H_, 256>>>(qkv_p, policy, att_p);

    // LIF(theta=0.5) in place
    lif_kernel<<<(BCN / 4 + 255) / 256, 256>>>(att_p, att_p, 0.5f, BCN / 4);

    // spikes -> K-major fp16 (exact)
    strans<<<dim3(JTOT / 64, C_ / 64), 256>>>(att_p);

    // proj GEMM: [384x384] @ [384x25088], A split, B exact (2 products) -> qkv scratch
    gemm_mma<1><<<dim3(JTOT / 128, 384 / 64), 256, SM1>>>(
        pws_p, (size_t)WPRJ, ss_p, (size_t)0, ps_p, pbs_p, qkv_p);

    // final LIF(theta=1) -> d_out
    lif_kernel<<<(BCN / 4 + 255) / 256, 256>>>(qkv_p, (float*)d_out, 1.0f, BCN / 4);
}